// round 2
// baseline (speedup 1.0000x reference)
#include <cuda_runtime.h>
#include <math.h>

#define NVV 778
#define NC   146      // 1 + 10 beta + 135 pose_feature
#define NCOL 784      // 768 joint cols + 15 finger cols + 1 pad
#define BMAX 4096

// ---- scratch (static device globals; no allocation) ----
__device__ float g_S[256];          // S[k*16+j] = sum_v Jreg[v,k]*w[v,j]
__device__ float g_C[NC * NCOL];    // factored basis matrix
__device__ float g_JT[11 * 48];     // rest-joint basis: [1+10][16*3]
__device__ float g_X[BMAX * NC];    // per-batch feature vector [1, beta, pf]
__device__ float g_A[BMAX * 192];   // per-batch skinning transforms 16 x (R9 + t3)
__device__ float g_M[BMAX * NCOL];  // GEMM result

__constant__ int c_par[16]   = {-1,0,1,2,0,4,5,0,7,8,0,10,11,0,13,14};
__constant__ int c_depth[16] = {0,1,2,3,1,2,3,1,2,3,1,2,3,1,2,3};
__constant__ int c_fidx[5]   = {734,333,443,555,678};

// ============================================================
// kC: C[r, (k*16+j)*3+c] = sum_v Jreg[v,k]*w[v,j]*D[r, v*3+c]
//     D[0]=v_template, D[1..10]=shapedirs, D[11..145]=posedirs
//     + finger columns 768..782 : D[r, fidx*3+c] (direct copy)
//     + block r==0 also writes S.
// grid: NC blocks x 256 threads (thread = (k,j))
// ============================================================
__global__ void kC(const float* __restrict__ vt, const float* __restrict__ sd,
                   const float* __restrict__ pd, const float* __restrict__ Jreg,
                   const float* __restrict__ Wt) {
    __shared__ float Ds[NVV * 3];
    int r = blockIdx.x, t = threadIdx.x;
    const float* src = (r == 0) ? vt : (r < 11 ? sd + (r - 1) * (NVV * 3)
                                               : pd + (r - 11) * (NVV * 3));
    for (int i = t; i < NVV * 3; i += 256) Ds[i] = src[i];
    __syncthreads();
    int k = t >> 4, j = t & 15;
    float a0 = 0.f, a1 = 0.f, a2 = 0.f, ssum = 0.f;
    #pragma unroll 2
    for (int v = 0; v < NVV; ++v) {
        float e = Jreg[v * 16 + k] * Wt[v * 16 + j];
        ssum += e;
        a0 += e * Ds[3 * v + 0];
        a1 += e * Ds[3 * v + 1];
        a2 += e * Ds[3 * v + 2];
    }
    float* out = g_C + r * NCOL;
    out[t * 3 + 0] = a0;
    out[t * 3 + 1] = a1;
    out[t * 3 + 2] = a2;
    if (t < 15) out[768 + t] = Ds[c_fidx[t / 3] * 3 + (t % 3)];
    if (t == 15) out[783] = 0.f;
    if (r == 0) g_S[t] = ssum;
}

// ============================================================
// kJT: JT[r, j*3+c] = sum_v Jreg[v,j]*D[r, v*3+c], r in [0,11)
// grid: 11 blocks x 256 threads (first 48 compute)
// ============================================================
__global__ void kJT(const float* __restrict__ vt, const float* __restrict__ sd,
                    const float* __restrict__ Jreg) {
    __shared__ float Ds[NVV * 3];
    int r = blockIdx.x, t = threadIdx.x;
    const float* src = (r == 0) ? vt : sd + (r - 1) * (NVV * 3);
    for (int i = t; i < NVV * 3; i += 256) Ds[i] = src[i];
    __syncthreads();
    if (t < 48) {
        int j = t / 3, c = t % 3;
        float acc = 0.f;
        #pragma unroll 2
        for (int v = 0; v < NVV; ++v) acc += Jreg[v * 16 + j] * Ds[3 * v + c];
        g_JT[r * 48 + t] = acc;
    }
}

// ============================================================
// kBatch: per-batch kinematics. One warp per batch item.
//  - full_local = theta[3:48] @ hc + mean  -> pose(48)
//  - Rodrigues per joint (lanes 0..15), pose_feature -> g_X
//  - rest joints J from JT basis
//  - kinematic chain by depth levels -> A (R,t), minus init bone -> g_A
// ============================================================
__global__ void kBatch(const float* __restrict__ beta, const float* __restrict__ theta,
                       const float* __restrict__ hm, const float* __restrict__ hc, int B) {
    __shared__ float hcs[45 * 45];
    __shared__ float hms[45];
    __shared__ float JTs[11 * 48];
    __shared__ float wsPose[8][48];
    __shared__ float wsA[8][16 * 12];
    __shared__ float wsJ[8][48];
    __shared__ float wsBeta[8][10];

    int tid = threadIdx.x, warp = tid >> 5, lane = tid & 31;
    for (int i = tid; i < 2025; i += 256) hcs[i] = hc[i];
    if (tid < 45) hms[tid] = hm[tid];
    for (int i = tid; i < 528; i += 256) JTs[i] = g_JT[i];
    __syncthreads();

    int b = blockIdx.x * 8 + warp;
    if (b >= B) return;

    float* P = wsPose[warp];
    const float* th = theta + b * 48;
    if (lane < 16) { P[lane] = th[lane]; P[lane + 16] = th[lane + 16]; P[lane + 32] = th[lane + 32]; }
    if (lane < 10) wsBeta[warp][lane] = beta[b * 10 + lane];
    __syncwarp();

    // full_local: outputs i0 = lane (0..31), i1 = lane+32 (lanes 0..12)
    int i0 = lane, i1 = lane + 32;
    float acc0 = hms[i0];
    float acc1 = (i1 < 45) ? hms[i1] : 0.f;
    #pragma unroll 5
    for (int p = 0; p < 45; ++p) {
        float tv = P[3 + p];
        acc0 += tv * hcs[p * 45 + i0];
        if (i1 < 45) acc1 += tv * hcs[p * 45 + i1];
    }
    __syncwarp();               // everyone done reading theta part of P
    P[3 + i0] = acc0;
    if (i1 < 45) P[3 + i1] = acc1;
    __syncwarp();

    // Rodrigues (lanes 0..15); also emit x-vector
    float R[9];
    if (lane < 16) {
        float rx = P[3 * lane], ry = P[3 * lane + 1], rz = P[3 * lane + 2];
        float ex = rx + 1e-8f, ey = ry + 1e-8f, ez = rz + 1e-8f;
        float ang = sqrtf(ex * ex + ey * ey + ez * ez);
        float inv = 1.0f / ang;
        float ax = rx * inv, ay = ry * inv, az = rz * inv;
        float s, co;
        sincosf(ang, &s, &co);
        float t1 = 1.0f - co;
        R[0] = 1.0f - t1 * (ay * ay + az * az);
        R[1] = -s * az + t1 * ax * ay;
        R[2] =  s * ay + t1 * ax * az;
        R[3] =  s * az + t1 * ax * ay;
        R[4] = 1.0f - t1 * (ax * ax + az * az);
        R[5] = -s * ax + t1 * ay * az;
        R[6] = -s * ay + t1 * ax * az;
        R[7] =  s * ax + t1 * ay * az;
        R[8] = 1.0f - t1 * (ax * ax + ay * ay);
        if (lane >= 1) {
            float* xp = g_X + b * NC + 11 + (lane - 1) * 9;
            #pragma unroll
            for (int e = 0; e < 9; ++e)
                xp[e] = R[e] - ((e == 0 || e == 4 || e == 8) ? 1.0f : 0.0f);
        }
    }
    if (lane == 0) g_X[b * NC] = 1.0f;
    if (lane < 10) g_X[b * NC + 1 + lane] = wsBeta[warp][lane];
    __syncwarp();

    // rest joints J (48 outputs)
    float* Jv = wsJ[warp];
    for (int o = lane; o < 48; o += 32) {
        float acc = JTs[o];
        #pragma unroll
        for (int s2 = 0; s2 < 10; ++s2) acc += wsBeta[warp][s2] * JTs[(s2 + 1) * 48 + o];
        Jv[o] = acc;
    }
    __syncwarp();

    // kinematic chain by depth level
    float AR[9], At[3];
    float tl0 = 0.f, tl1 = 0.f, tl2 = 0.f;
    if (lane < 16) {
        int par = c_par[lane];
        if (lane == 0) { tl0 = Jv[0]; tl1 = Jv[1]; tl2 = Jv[2]; }
        else {
            tl0 = Jv[3 * lane + 0] - Jv[3 * par + 0];
            tl1 = Jv[3 * lane + 1] - Jv[3 * par + 1];
            tl2 = Jv[3 * lane + 2] - Jv[3 * par + 2];
        }
    }
    float* Aw = wsA[warp];
    if (lane == 0) {
        #pragma unroll
        for (int e = 0; e < 9; ++e) { AR[e] = R[e]; Aw[e] = R[e]; }
        At[0] = tl0; At[1] = tl1; At[2] = tl2;
        Aw[9] = tl0; Aw[10] = tl1; Aw[11] = tl2;
    }
    __syncwarp();
    for (int level = 1; level <= 3; ++level) {
        if (lane < 16 && c_depth[lane] == level) {
            int par = c_par[lane];
            float Pp[12];
            #pragma unroll
            for (int e = 0; e < 12; ++e) Pp[e] = Aw[par * 12 + e];
            #pragma unroll
            for (int rr = 0; rr < 3; ++rr)
                #pragma unroll
                for (int cc = 0; cc < 3; ++cc)
                    AR[rr * 3 + cc] = Pp[rr * 3 + 0] * R[0 + cc] +
                                      Pp[rr * 3 + 1] * R[3 + cc] +
                                      Pp[rr * 3 + 2] * R[6 + cc];
            At[0] = Pp[0] * tl0 + Pp[1] * tl1 + Pp[2] * tl2 + Pp[9];
            At[1] = Pp[3] * tl0 + Pp[4] * tl1 + Pp[5] * tl2 + Pp[10];
            At[2] = Pp[6] * tl0 + Pp[7] * tl1 + Pp[8] * tl2 + Pp[11];
            #pragma unroll
            for (int e = 0; e < 9; ++e) Aw[lane * 12 + e] = AR[e];
            Aw[lane * 12 + 9] = At[0]; Aw[lane * 12 + 10] = At[1]; Aw[lane * 12 + 11] = At[2];
        }
        __syncwarp();
    }
    if (lane < 16) {
        float jx = Jv[3 * lane], jy = Jv[3 * lane + 1], jz = Jv[3 * lane + 2];
        At[0] -= AR[0] * jx + AR[1] * jy + AR[2] * jz;
        At[1] -= AR[3] * jx + AR[4] * jy + AR[5] * jz;
        At[2] -= AR[6] * jx + AR[7] * jy + AR[8] * jz;
        float* ap = g_A + b * 192 + lane * 12;
        #pragma unroll
        for (int e = 0; e < 9; ++e) ap[e] = AR[e];
        ap[9] = At[0]; ap[10] = At[1]; ap[11] = At[2];
    }
}

// ============================================================
// kGemm: M[b, 0..783] = X[b, 0..145] @ C[146 x 784]
// Tiles: 64 batch x 112 cols per CTA, K chunks of 50, 4x7 per thread.
// ============================================================
#define TBm 64
#define TNn 112
#define KCH 50
__global__ void kGemm(int B) {
    __shared__ float Xs[KCH][68];    // [k-chunk][batch], padded
    __shared__ float Cs[KCH][TNn];
    int b0 = blockIdx.x * TBm, n0 = blockIdx.y * TNn;
    int tid = threadIdx.x;
    int tm = tid & 15, tn = tid >> 4;
    float acc[4][7];
    #pragma unroll
    for (int a = 0; a < 4; ++a)
        #pragma unroll
        for (int c = 0; c < 7; ++c) acc[a][c] = 0.f;

    for (int r0 = 0; r0 < NC; r0 += KCH) {
        int rc = NC - r0; if (rc > KCH) rc = KCH;
        __syncthreads();
        for (int i = tid; i < TBm * KCH; i += 256) {
            int m = i / KCH, rr = i - m * KCH;
            float val = 0.f;
            if (rr < rc && (b0 + m) < B) val = g_X[(b0 + m) * NC + r0 + rr];
            Xs[rr][m] = val;
        }
        for (int i = tid; i < TNn * KCH; i += 256) {
            int rr = i / TNn, nn = i - rr * TNn;
            float val = 0.f;
            if (rr < rc) val = g_C[(r0 + rr) * NCOL + n0 + nn];
            Cs[rr][nn] = val;
        }
        __syncthreads();
        #pragma unroll 2
        for (int rr = 0; rr < KCH; ++rr) {
            float4 xv = *(const float4*)&Xs[rr][tm * 4];
            float cv[7];
            #pragma unroll
            for (int i = 0; i < 7; ++i) cv[i] = Cs[rr][tn * 7 + i];
            #pragma unroll
            for (int i = 0; i < 7; ++i) {
                acc[0][i] += xv.x * cv[i];
                acc[1][i] += xv.y * cv[i];
                acc[2][i] += xv.z * cv[i];
                acc[3][i] += xv.w * cv[i];
            }
        }
    }
    #pragma unroll
    for (int a = 0; a < 4; ++a) {
        int b = b0 + tm * 4 + a;
        if (b >= B) continue;
        #pragma unroll
        for (int i = 0; i < 7; ++i)
            g_M[b * NCOL + n0 + tn * 7 + i] = acc[a][i];
    }
}

// ============================================================
// kOut: assemble 21x3 joints per batch item. One warp per item.
// ============================================================
__global__ void kOut(const float* __restrict__ Wt, float* __restrict__ out, int B) {
    __shared__ float Ssm[256];
    __shared__ float Ms[8][784];
    __shared__ float As[8][192];
    int tid = threadIdx.x, warp = tid >> 5, lane = tid & 31;
    Ssm[tid] = g_S[tid];
    __syncthreads();
    int b = blockIdx.x * 8 + warp;
    if (b >= B) return;
    for (int i = lane; i < 784; i += 32) Ms[warp][i] = g_M[b * 784 + i];
    for (int i = lane; i < 192; i += 32) As[warp][i] = g_A[b * 192 + i];
    __syncwarp();
    if (lane < 21) {
        float a0 = 0.f, a1 = 0.f, a2 = 0.f;
        if (lane < 16) {
            int k = lane;
            #pragma unroll
            for (int j = 0; j < 16; ++j) {
                const float* Aj = &As[warp][j * 12];
                float s = Ssm[k * 16 + j];
                int base = (k * 16 + j) * 3;
                float m0 = Ms[warp][base], m1 = Ms[warp][base + 1], m2 = Ms[warp][base + 2];
                a0 += Aj[0] * m0 + Aj[1] * m1 + Aj[2] * m2 + Aj[9]  * s;
                a1 += Aj[3] * m0 + Aj[4] * m1 + Aj[5] * m2 + Aj[10] * s;
                a2 += Aj[6] * m0 + Aj[7] * m1 + Aj[8] * m2 + Aj[11] * s;
            }
        } else {
            int f = lane - 16;
            float v0 = Ms[warp][768 + f * 3], v1 = Ms[warp][768 + f * 3 + 1], v2 = Ms[warp][768 + f * 3 + 2];
            const float* wr = Wt + c_fidx[f] * 16;
            #pragma unroll
            for (int j = 0; j < 16; ++j) {
                const float* Aj = &As[warp][j * 12];
                float w = wr[j];
                a0 += w * (Aj[0] * v0 + Aj[1] * v1 + Aj[2] * v2 + Aj[9]);
                a1 += w * (Aj[3] * v0 + Aj[4] * v1 + Aj[5] * v2 + Aj[10]);
                a2 += w * (Aj[6] * v0 + Aj[7] * v1 + Aj[8] * v2 + Aj[11]);
            }
        }
        float* op = out + b * 63 + lane * 3;
        op[0] = a0; op[1] = a1; op[2] = a2;
    }
}

// ============================================================
extern "C" void kernel_launch(void* const* d_in, const int* in_sizes, int n_in,
                              void* d_out, int out_size) {
    const float* beta  = (const float*)d_in[0];
    const float* theta = (const float*)d_in[1];
    const float* vt    = (const float*)d_in[2];
    const float* sd    = (const float*)d_in[3];
    const float* pd    = (const float*)d_in[4];
    const float* Jreg  = (const float*)d_in[5];
    const float* W     = (const float*)d_in[6];
    const float* hm    = (const float*)d_in[7];
    const float* hc    = (const float*)d_in[8];
    int B = in_sizes[0] / 10;
    if (B > BMAX) B = BMAX;

    kC<<<NC, 256>>>(vt, sd, pd, Jreg, W);
    kJT<<<11, 256>>>(vt, sd, Jreg);
    kBatch<<<(B + 7) / 8, 256>>>(beta, theta, hm, hc, B);
    kGemm<<<dim3((B + TBm - 1) / TBm, NCOL / TNn), 256>>>(B);
    kOut<<<(B + 7) / 8, 256>>>(W, (float*)d_out, B);
}

// round 3
// speedup vs baseline: 1.6789x; 1.6789x over previous
#include <cuda_runtime.h>
#include <math.h>

#define NVV 778
#define NC   146      // 1 + 10 beta + 135 pose_feature
#define NCOL 784      // 768 joint cols + 15 finger cols + 1 pad
#define BMAX 4096

// ---- scratch (static device globals; no allocation) ----
__device__ float g_S[256];          // S[k*16+j] = sum_v Jreg[v,k]*w[v,j]
__device__ float g_C[NC * NCOL];    // factored basis matrix
__device__ float g_JT[11 * 48];     // rest-joint basis: [1+10][16*3]
__device__ float g_X[BMAX * NC];    // per-batch feature vector [1, beta, pf]
__device__ float g_A[BMAX * 192];   // per-batch skinning transforms 16 x (R9 + t3)
__device__ float g_M[BMAX * NCOL];  // GEMM result

__constant__ int c_par[16]   = {-1,0,1,2,0,4,5,0,7,8,0,10,11,0,13,14};
__constant__ int c_depth[16] = {0,1,2,3,1,2,3,1,2,3,1,2,3,1,2,3};
__constant__ int c_fidx[5]   = {734,333,443,555,678};

// ============================================================
// kC: C[r, (k*16+j)*3+c] = sum_v Jreg[v,k]*w[v,j]*D[r, v*3+c]
//     All inner-loop operands staged through shared memory in
//     chunks of 112 vertices. JT (r<11) and S (r==0) fused in.
// grid: NC blocks x 256 threads (thread = (k,j))
// ============================================================
#define CHV 112
__global__ void __launch_bounds__(256) kC(
        const float* __restrict__ vt, const float* __restrict__ sd,
        const float* __restrict__ pd, const float* __restrict__ Jreg,
        const float* __restrict__ Wt) {
    __shared__ float Ds[CHV * 3];
    __shared__ float Jr[CHV * 16];
    __shared__ float Wc[CHV * 16];
    int r = blockIdx.x, t = threadIdx.x;
    const float* src = (r == 0) ? vt : (r < 11 ? sd + (r - 1) * (NVV * 3)
                                               : pd + (r - 11) * (NVV * 3));
    int k = t >> 4, j = t & 15;
    int jj = t / 3, cc = t - jj * 3;          // for JT (t<48)
    int fgi = (t < 15) ? (c_fidx[t / 3] * 3 + (t % 3)) : -1;
    float a0 = 0.f, a1 = 0.f, a2 = 0.f, ss = 0.f, jt = 0.f, fingv = 0.f;

    for (int v0 = 0; v0 < NVV; v0 += CHV) {
        int n = NVV - v0; if (n > CHV) n = CHV;
        __syncthreads();
        for (int i = t; i < n * 3; i += 256) Ds[i] = src[v0 * 3 + i];
        for (int i = t; i < n * 16; i += 256) {
            Jr[i] = Jreg[v0 * 16 + i];
            Wc[i] = Wt[v0 * 16 + i];
        }
        __syncthreads();
        #pragma unroll 4
        for (int v = 0; v < n; ++v) {
            float e = Jr[v * 16 + k] * Wc[v * 16 + j];
            ss += e;
            a0 += e * Ds[v * 3 + 0];
            a1 += e * Ds[v * 3 + 1];
            a2 += e * Ds[v * 3 + 2];
        }
        if (r < 11 && t < 48) {
            #pragma unroll 4
            for (int v = 0; v < n; ++v) jt += Jr[v * 16 + jj] * Ds[v * 3 + cc];
        }
        if (fgi >= 0 && fgi >= v0 * 3 && fgi < (v0 + n) * 3) fingv = Ds[fgi - v0 * 3];
    }
    float* out = g_C + r * NCOL;
    out[t * 3 + 0] = a0;
    out[t * 3 + 1] = a1;
    out[t * 3 + 2] = a2;
    if (t < 15) out[768 + t] = fingv;
    if (t == 15) out[783] = 0.f;
    if (r == 0) g_S[t] = ss;
    if (r < 11 && t < 48) g_JT[r * 48 + t] = jt;
}

// ============================================================
// kBatch: per-batch kinematics. One warp per batch item.
// ============================================================
__global__ void kBatch(const float* __restrict__ beta, const float* __restrict__ theta,
                       const float* __restrict__ hm, const float* __restrict__ hc, int B) {
    __shared__ float hcs[45 * 45];
    __shared__ float hms[45];
    __shared__ float JTs[11 * 48];
    __shared__ float wsPose[8][48];
    __shared__ float wsA[8][16 * 12];
    __shared__ float wsJ[8][48];
    __shared__ float wsBeta[8][10];

    int tid = threadIdx.x, warp = tid >> 5, lane = tid & 31;
    for (int i = tid; i < 2025; i += 256) hcs[i] = hc[i];
    if (tid < 45) hms[tid] = hm[tid];
    for (int i = tid; i < 528; i += 256) JTs[i] = g_JT[i];
    __syncthreads();

    int b = blockIdx.x * 8 + warp;
    if (b >= B) return;

    float* P = wsPose[warp];
    const float* th = theta + b * 48;
    if (lane < 16) { P[lane] = th[lane]; P[lane + 16] = th[lane + 16]; P[lane + 32] = th[lane + 32]; }
    if (lane < 10) wsBeta[warp][lane] = beta[b * 10 + lane];
    __syncwarp();

    int i0 = lane, i1 = lane + 32;
    float acc0 = hms[i0];
    float acc1 = (i1 < 45) ? hms[i1] : 0.f;
    #pragma unroll 5
    for (int p = 0; p < 45; ++p) {
        float tv = P[3 + p];
        acc0 += tv * hcs[p * 45 + i0];
        if (i1 < 45) acc1 += tv * hcs[p * 45 + i1];
    }
    __syncwarp();
    P[3 + i0] = acc0;
    if (i1 < 45) P[3 + i1] = acc1;
    __syncwarp();

    float R[9];
    if (lane < 16) {
        float rx = P[3 * lane], ry = P[3 * lane + 1], rz = P[3 * lane + 2];
        float ex = rx + 1e-8f, ey = ry + 1e-8f, ez = rz + 1e-8f;
        float ang = sqrtf(ex * ex + ey * ey + ez * ez);
        float inv = 1.0f / ang;
        float ax = rx * inv, ay = ry * inv, az = rz * inv;
        float s, co;
        sincosf(ang, &s, &co);
        float t1 = 1.0f - co;
        R[0] = 1.0f - t1 * (ay * ay + az * az);
        R[1] = -s * az + t1 * ax * ay;
        R[2] =  s * ay + t1 * ax * az;
        R[3] =  s * az + t1 * ax * ay;
        R[4] = 1.0f - t1 * (ax * ax + az * az);
        R[5] = -s * ax + t1 * ay * az;
        R[6] = -s * ay + t1 * ax * az;
        R[7] =  s * ax + t1 * ay * az;
        R[8] = 1.0f - t1 * (ax * ax + ay * ay);
        if (lane >= 1) {
            float* xp = g_X + b * NC + 11 + (lane - 1) * 9;
            #pragma unroll
            for (int e = 0; e < 9; ++e)
                xp[e] = R[e] - ((e == 0 || e == 4 || e == 8) ? 1.0f : 0.0f);
        }
    }
    if (lane == 0) g_X[b * NC] = 1.0f;
    if (lane < 10) g_X[b * NC + 1 + lane] = wsBeta[warp][lane];
    __syncwarp();

    float* Jv = wsJ[warp];
    for (int o = lane; o < 48; o += 32) {
        float acc = JTs[o];
        #pragma unroll
        for (int s2 = 0; s2 < 10; ++s2) acc += wsBeta[warp][s2] * JTs[(s2 + 1) * 48 + o];
        Jv[o] = acc;
    }
    __syncwarp();

    float AR[9], At[3];
    float tl0 = 0.f, tl1 = 0.f, tl2 = 0.f;
    if (lane < 16) {
        int par = c_par[lane];
        if (lane == 0) { tl0 = Jv[0]; tl1 = Jv[1]; tl2 = Jv[2]; }
        else {
            tl0 = Jv[3 * lane + 0] - Jv[3 * par + 0];
            tl1 = Jv[3 * lane + 1] - Jv[3 * par + 1];
            tl2 = Jv[3 * lane + 2] - Jv[3 * par + 2];
        }
    }
    float* Aw = wsA[warp];
    if (lane == 0) {
        #pragma unroll
        for (int e = 0; e < 9; ++e) { AR[e] = R[e]; Aw[e] = R[e]; }
        At[0] = tl0; At[1] = tl1; At[2] = tl2;
        Aw[9] = tl0; Aw[10] = tl1; Aw[11] = tl2;
    }
    __syncwarp();
    for (int level = 1; level <= 3; ++level) {
        if (lane < 16 && c_depth[lane] == level) {
            int par = c_par[lane];
            float Pp[12];
            #pragma unroll
            for (int e = 0; e < 12; ++e) Pp[e] = Aw[par * 12 + e];
            #pragma unroll
            for (int rr = 0; rr < 3; ++rr)
                #pragma unroll
                for (int ccx = 0; ccx < 3; ++ccx)
                    AR[rr * 3 + ccx] = Pp[rr * 3 + 0] * R[0 + ccx] +
                                       Pp[rr * 3 + 1] * R[3 + ccx] +
                                       Pp[rr * 3 + 2] * R[6 + ccx];
            At[0] = Pp[0] * tl0 + Pp[1] * tl1 + Pp[2] * tl2 + Pp[9];
            At[1] = Pp[3] * tl0 + Pp[4] * tl1 + Pp[5] * tl2 + Pp[10];
            At[2] = Pp[6] * tl0 + Pp[7] * tl1 + Pp[8] * tl2 + Pp[11];
            #pragma unroll
            for (int e = 0; e < 9; ++e) Aw[lane * 12 + e] = AR[e];
            Aw[lane * 12 + 9] = At[0]; Aw[lane * 12 + 10] = At[1]; Aw[lane * 12 + 11] = At[2];
        }
        __syncwarp();
    }
    if (lane < 16) {
        float jx = Jv[3 * lane], jy = Jv[3 * lane + 1], jz = Jv[3 * lane + 2];
        At[0] -= AR[0] * jx + AR[1] * jy + AR[2] * jz;
        At[1] -= AR[3] * jx + AR[4] * jy + AR[5] * jz;
        At[2] -= AR[6] * jx + AR[7] * jy + AR[8] * jz;
        float* ap = g_A + b * 192 + lane * 12;
        #pragma unroll
        for (int e = 0; e < 9; ++e) ap[e] = AR[e];
        ap[9] = At[0]; ap[10] = At[1]; ap[11] = At[2];
    }
}

// ============================================================
// kGemm: M[4096 x 784] = X[4096 x 146] @ C[146 x 784]
// 128x112 CTA tile, 8m x 7n per thread, packed fma.rn.f32x2
// over batch pairs; C duplicated in smem ([k][i][tn] layout,
// conflict-free LDS.64). Grid 32x7 = 224 CTAs = 1 wave @2/SM.
// ============================================================
#define TBm 128
#define TNn 112
#define KCH 32

__device__ __forceinline__ void ffma2(unsigned long long& d,
                                      unsigned long long a,
                                      unsigned long long b) {
    asm("fma.rn.f32x2 %0, %1, %2, %0;" : "+l"(d) : "l"(a), "l"(b));
}

__global__ void __launch_bounds__(256, 2) kGemm(int B) {
    __shared__ float Xs[KCH][TBm];                       // 16 KB
    __shared__ unsigned long long Cs[KCH][TNn];          // 28 KB (dup pairs)
    int b0 = blockIdx.x * TBm, n0 = blockIdx.y * TNn;
    int tid = threadIdx.x;
    int tm = tid >> 4, tn = tid & 15;                    // 16 x 16

    unsigned long long acc[4][7];
    #pragma unroll
    for (int p = 0; p < 4; ++p)
        #pragma unroll
        for (int i = 0; i < 7; ++i) acc[p][i] = 0ull;

    for (int r0 = 0; r0 < NC; r0 += KCH) {
        int rc = NC - r0; if (rc > KCH) rc = KCH;
        __syncthreads();
        // Xs[rr][m], coalesced over rr (KCH==32 matches warp width)
        #pragma unroll
        for (int i = tid; i < TBm * KCH; i += 256) {
            int m = i >> 5, rr = i & 31;
            float val = 0.f;
            if (rr < rc && (b0 + m) < B) val = g_X[(b0 + m) * NC + r0 + rr];
            Xs[rr][m] = val;
        }
        // Cs[rr][i*16+tn] holds duplicated column (n0 + tn*7 + i)
        for (int i2 = tid; i2 < TNn * KCH; i2 += 256) {
            int rr = i2 / TNn, nn = i2 - rr * TNn;
            float val = 0.f;
            if (rr < rc) val = g_C[(r0 + rr) * NCOL + n0 + nn];
            unsigned u = __float_as_uint(val);
            Cs[rr][(nn % 7) * 16 + (nn / 7)] = ((unsigned long long)u << 32) | u;
        }
        __syncthreads();
        #pragma unroll 4
        for (int rr = 0; rr < KCH; ++rr) {
            unsigned long long xp[4];
            #pragma unroll
            for (int p = 0; p < 4; ++p)
                xp[p] = *(const unsigned long long*)&Xs[rr][tm * 8 + 2 * p];
            unsigned long long cv[7];
            #pragma unroll
            for (int i = 0; i < 7; ++i) cv[i] = Cs[rr][i * 16 + tn];
            #pragma unroll
            for (int p = 0; p < 4; ++p)
                #pragma unroll
                for (int i = 0; i < 7; ++i)
                    ffma2(acc[p][i], xp[p], cv[i]);
        }
    }
    #pragma unroll
    for (int p = 0; p < 4; ++p) {
        int row0 = b0 + tm * 8 + 2 * p;
        if (row0 >= B) continue;
        #pragma unroll
        for (int i = 0; i < 7; ++i) {
            int col = n0 + tn * 7 + i;
            float lo = __uint_as_float((unsigned)(acc[p][i] & 0xFFFFFFFFull));
            float hi = __uint_as_float((unsigned)(acc[p][i] >> 32));
            g_M[row0 * NCOL + col] = lo;
            if (row0 + 1 < B) g_M[(row0 + 1) * NCOL + col] = hi;
        }
    }
}

// ============================================================
// kOut: assemble 21x3 joints per batch item. One warp per item.
// ============================================================
__global__ void kOut(const float* __restrict__ Wt, float* __restrict__ out, int B) {
    __shared__ float Ssm[256];
    __shared__ float Ms[8][784];
    __shared__ float As[8][192];
    int tid = threadIdx.x, warp = tid >> 5, lane = tid & 31;
    Ssm[tid] = g_S[tid];
    __syncthreads();
    int b = blockIdx.x * 8 + warp;
    if (b >= B) return;
    for (int i = lane; i < 784; i += 32) Ms[warp][i] = g_M[b * 784 + i];
    for (int i = lane; i < 192; i += 32) As[warp][i] = g_A[b * 192 + i];
    __syncwarp();
    if (lane < 21) {
        float a0 = 0.f, a1 = 0.f, a2 = 0.f;
        if (lane < 16) {
            int k = lane;
            #pragma unroll
            for (int j = 0; j < 16; ++j) {
                const float* Aj = &As[warp][j * 12];
                float s = Ssm[k * 16 + j];
                int base = (k * 16 + j) * 3;
                float m0 = Ms[warp][base], m1 = Ms[warp][base + 1], m2 = Ms[warp][base + 2];
                a0 += Aj[0] * m0 + Aj[1] * m1 + Aj[2] * m2 + Aj[9]  * s;
                a1 += Aj[3] * m0 + Aj[4] * m1 + Aj[5] * m2 + Aj[10] * s;
                a2 += Aj[6] * m0 + Aj[7] * m1 + Aj[8] * m2 + Aj[11] * s;
            }
        } else {
            int f = lane - 16;
            float v0 = Ms[warp][768 + f * 3], v1 = Ms[warp][768 + f * 3 + 1], v2 = Ms[warp][768 + f * 3 + 2];
            const float* wr = Wt + c_fidx[f] * 16;
            #pragma unroll
            for (int j = 0; j < 16; ++j) {
                const float* Aj = &As[warp][j * 12];
                float w = wr[j];
                a0 += w * (Aj[0] * v0 + Aj[1] * v1 + Aj[2] * v2 + Aj[9]);
                a1 += w * (Aj[3] * v0 + Aj[4] * v1 + Aj[5] * v2 + Aj[10]);
                a2 += w * (Aj[6] * v0 + Aj[7] * v1 + Aj[8] * v2 + Aj[11]);
            }
        }
        float* op = out + b * 63 + lane * 3;
        op[0] = a0; op[1] = a1; op[2] = a2;
    }
}

// ============================================================
extern "C" void kernel_launch(void* const* d_in, const int* in_sizes, int n_in,
                              void* d_out, int out_size) {
    const float* beta  = (const float*)d_in[0];
    const float* theta = (const float*)d_in[1];
    const float* vt    = (const float*)d_in[2];
    const float* sd    = (const float*)d_in[3];
    const float* pd    = (const float*)d_in[4];
    const float* Jreg  = (const float*)d_in[5];
    const float* W     = (const float*)d_in[6];
    const float* hm    = (const float*)d_in[7];
    const float* hc    = (const float*)d_in[8];
    int B = in_sizes[0] / 10;
    if (B > BMAX) B = BMAX;

    kC<<<NC, 256>>>(vt, sd, pd, Jreg, W);
    kBatch<<<(B + 7) / 8, 256>>>(beta, theta, hm, hc, B);
    kGemm<<<dim3((B + TBm - 1) / TBm, NCOL / TNn), 256>>>(B);
    kOut<<<(B + 7) / 8, 256>>>(W, (float*)d_out, B);
}

// round 6
// speedup vs baseline: 1.7098x; 1.0184x over previous
#include <cuda_runtime.h>
#include <cuda_bf16.h>
#include <cstdint>
#include <math.h>

#define NVV 778
#define NC   146      // 1 + 10 beta + 135 pose_feature
#define NCOL 784      // 768 joint cols + 15 finger cols + 1 pad
#define BMAX 4096
#define KP   448      // split-K: [Xh(146)|Xh(146)|Xl(146)|pad2]
#define KPAD 456      // smem row stride in halves (pad 8 -> conflict-free)

// ---- scratch (static device globals; no allocation) ----
__device__ float g_S[256];
__device__ float g_C[NC * NCOL];
__device__ float g_JT[11 * 48];
__device__ float g_X[BMAX * NC];
__device__ float g_A[BMAX * 192];
__device__ float g_M[BMAX * NCOL];
__device__ __nv_bfloat16 g_Xb[BMAX * KP];   // split-bf16 X, row-major [b][kp]
__device__ __nv_bfloat16 g_Ct[NCOL * KP];   // split-bf16 C^T, row-major [n][kp]

__constant__ int c_par[16]   = {-1,0,1,2,0,4,5,0,7,8,0,10,11,0,13,14};
__constant__ int c_depth[16] = {0,1,2,3,1,2,3,1,2,3,1,2,3,1,2,3};
__constant__ int c_fidx[5]   = {734,333,443,555,678};

// ============================================================
// kC: factored basis matrix (known-good since R3)
// ============================================================
#define CHV 112
__global__ void __launch_bounds__(256) kC(
        const float* __restrict__ vt, const float* __restrict__ sd,
        const float* __restrict__ pd, const float* __restrict__ Jreg,
        const float* __restrict__ Wt) {
    __shared__ float Ds[CHV * 3];
    __shared__ float Jr[CHV * 16];
    __shared__ float Wc[CHV * 16];
    int r = blockIdx.x, t = threadIdx.x;
    const float* src = (r == 0) ? vt : (r < 11 ? sd + (r - 1) * (NVV * 3)
                                               : pd + (r - 11) * (NVV * 3));
    int k = t >> 4, j = t & 15;
    int jj = t / 3, cc = t - jj * 3;
    int fgi = (t < 15) ? (c_fidx[t / 3] * 3 + (t % 3)) : -1;
    float a0 = 0.f, a1 = 0.f, a2 = 0.f, ss = 0.f, jt = 0.f, fingv = 0.f;

    for (int v0 = 0; v0 < NVV; v0 += CHV) {
        int n = NVV - v0; if (n > CHV) n = CHV;
        __syncthreads();
        for (int i = t; i < n * 3; i += 256) Ds[i] = src[v0 * 3 + i];
        for (int i = t; i < n * 16; i += 256) {
            Jr[i] = Jreg[v0 * 16 + i];
            Wc[i] = Wt[v0 * 16 + i];
        }
        __syncthreads();
        #pragma unroll 4
        for (int v = 0; v < n; ++v) {
            float e = Jr[v * 16 + k] * Wc[v * 16 + j];
            ss += e;
            a0 += e * Ds[v * 3 + 0];
            a1 += e * Ds[v * 3 + 1];
            a2 += e * Ds[v * 3 + 2];
        }
        if (r < 11 && t < 48) {
            #pragma unroll 4
            for (int v = 0; v < n; ++v) jt += Jr[v * 16 + jj] * Ds[v * 3 + cc];
        }
        if (fgi >= 0 && fgi >= v0 * 3 && fgi < (v0 + n) * 3) fingv = Ds[fgi - v0 * 3];
    }
    float* out = g_C + r * NCOL;
    out[t * 3 + 0] = a0;
    out[t * 3 + 1] = a1;
    out[t * 3 + 2] = a2;
    if (t < 15) out[768 + t] = fingv;
    if (t == 15) out[783] = 0.f;
    if (r == 0) g_S[t] = ss;
    if (r < 11 && t < 48) g_JT[r * 48 + t] = jt;
}

// ============================================================
// kBatch: per-batch kinematics (unchanged)
// ============================================================
__global__ void kBatch(const float* __restrict__ beta, const float* __restrict__ theta,
                       const float* __restrict__ hm, const float* __restrict__ hc, int B) {
    __shared__ float hcs[45 * 45];
    __shared__ float hms[45];
    __shared__ float JTs[11 * 48];
    __shared__ float wsPose[8][48];
    __shared__ float wsA[8][16 * 12];
    __shared__ float wsJ[8][48];
    __shared__ float wsBeta[8][10];

    int tid = threadIdx.x, warp = tid >> 5, lane = tid & 31;
    for (int i = tid; i < 2025; i += 256) hcs[i] = hc[i];
    if (tid < 45) hms[tid] = hm[tid];
    for (int i = tid; i < 528; i += 256) JTs[i] = g_JT[i];
    __syncthreads();

    int b = blockIdx.x * 8 + warp;
    if (b >= B) return;

    float* P = wsPose[warp];
    const float* th = theta + b * 48;
    if (lane < 16) { P[lane] = th[lane]; P[lane + 16] = th[lane + 16]; P[lane + 32] = th[lane + 32]; }
    if (lane < 10) wsBeta[warp][lane] = beta[b * 10 + lane];
    __syncwarp();

    int i0 = lane, i1 = lane + 32;
    float acc0 = hms[i0];
    float acc1 = (i1 < 45) ? hms[i1] : 0.f;
    #pragma unroll 5
    for (int p = 0; p < 45; ++p) {
        float tv = P[3 + p];
        acc0 += tv * hcs[p * 45 + i0];
        if (i1 < 45) acc1 += tv * hcs[p * 45 + i1];
    }
    __syncwarp();
    P[3 + i0] = acc0;
    if (i1 < 45) P[3 + i1] = acc1;
    __syncwarp();

    float R[9];
    if (lane < 16) {
        float rx = P[3 * lane], ry = P[3 * lane + 1], rz = P[3 * lane + 2];
        float ex = rx + 1e-8f, ey = ry + 1e-8f, ez = rz + 1e-8f;
        float ang = sqrtf(ex * ex + ey * ey + ez * ez);
        float inv = 1.0f / ang;
        float ax = rx * inv, ay = ry * inv, az = rz * inv;
        float s, co;
        sincosf(ang, &s, &co);
        float t1 = 1.0f - co;
        R[0] = 1.0f - t1 * (ay * ay + az * az);
        R[1] = -s * az + t1 * ax * ay;
        R[2] =  s * ay + t1 * ax * az;
        R[3] =  s * az + t1 * ax * ay;
        R[4] = 1.0f - t1 * (ax * ax + az * az);
        R[5] = -s * ax + t1 * ay * az;
        R[6] = -s * ay + t1 * ax * az;
        R[7] =  s * ax + t1 * ay * az;
        R[8] = 1.0f - t1 * (ax * ax + ay * ay);
        if (lane >= 1) {
            float* xp = g_X + b * NC + 11 + (lane - 1) * 9;
            #pragma unroll
            for (int e = 0; e < 9; ++e)
                xp[e] = R[e] - ((e == 0 || e == 4 || e == 8) ? 1.0f : 0.0f);
        }
    }
    if (lane == 0) g_X[b * NC] = 1.0f;
    if (lane < 10) g_X[b * NC + 1 + lane] = wsBeta[warp][lane];
    __syncwarp();

    float* Jv = wsJ[warp];
    for (int o = lane; o < 48; o += 32) {
        float acc = JTs[o];
        #pragma unroll
        for (int s2 = 0; s2 < 10; ++s2) acc += wsBeta[warp][s2] * JTs[(s2 + 1) * 48 + o];
        Jv[o] = acc;
    }
    __syncwarp();

    float AR[9], At[3];
    float tl0 = 0.f, tl1 = 0.f, tl2 = 0.f;
    if (lane < 16) {
        int par = c_par[lane];
        if (lane == 0) { tl0 = Jv[0]; tl1 = Jv[1]; tl2 = Jv[2]; }
        else {
            tl0 = Jv[3 * lane + 0] - Jv[3 * par + 0];
            tl1 = Jv[3 * lane + 1] - Jv[3 * par + 1];
            tl2 = Jv[3 * lane + 2] - Jv[3 * par + 2];
        }
    }
    float* Aw = wsA[warp];
    if (lane == 0) {
        #pragma unroll
        for (int e = 0; e < 9; ++e) { AR[e] = R[e]; Aw[e] = R[e]; }
        At[0] = tl0; At[1] = tl1; At[2] = tl2;
        Aw[9] = tl0; Aw[10] = tl1; Aw[11] = tl2;
    }
    __syncwarp();
    for (int level = 1; level <= 3; ++level) {
        if (lane < 16 && c_depth[lane] == level) {
            int par = c_par[lane];
            float Pp[12];
            #pragma unroll
            for (int e = 0; e < 12; ++e) Pp[e] = Aw[par * 12 + e];
            #pragma unroll
            for (int rr = 0; rr < 3; ++rr)
                #pragma unroll
                for (int ccx = 0; ccx < 3; ++ccx)
                    AR[rr * 3 + ccx] = Pp[rr * 3 + 0] * R[0 + ccx] +
                                       Pp[rr * 3 + 1] * R[3 + ccx] +
                                       Pp[rr * 3 + 2] * R[6 + ccx];
            At[0] = Pp[0] * tl0 + Pp[1] * tl1 + Pp[2] * tl2 + Pp[9];
            At[1] = Pp[3] * tl0 + Pp[4] * tl1 + Pp[5] * tl2 + Pp[10];
            At[2] = Pp[6] * tl0 + Pp[7] * tl1 + Pp[8] * tl2 + Pp[11];
            #pragma unroll
            for (int e = 0; e < 9; ++e) Aw[lane * 12 + e] = AR[e];
            Aw[lane * 12 + 9] = At[0]; Aw[lane * 12 + 10] = At[1]; Aw[lane * 12 + 11] = At[2];
        }
        __syncwarp();
    }
    if (lane < 16) {
        float jx = Jv[3 * lane], jy = Jv[3 * lane + 1], jz = Jv[3 * lane + 2];
        At[0] -= AR[0] * jx + AR[1] * jy + AR[2] * jz;
        At[1] -= AR[3] * jx + AR[4] * jy + AR[5] * jz;
        At[2] -= AR[6] * jx + AR[7] * jy + AR[8] * jz;
        float* ap = g_A + b * 192 + lane * 12;
        #pragma unroll
        for (int e = 0; e < 9; ++e) ap[e] = AR[e];
        ap[9] = At[0]; ap[10] = At[1]; ap[11] = At[2];
    }
}

// ============================================================
// kPrep: build bf16-split operands.
//  Xb[b][kp]: [Xh(146) | Xh(146) | Xl(146) | 0 0]
//  Ct[n][kp]: [Ch(146) | Cl(146) | Ch(146) | 0 0]
//  => dot(Xb, Ct) = Xh·Ch + Xh·Cl + Xl·Ch  (error ~ 2^-18)
// ============================================================
#define PREP_XBLK (BMAX * KP / 256)      // 7168
__global__ void kPrep(int B) {
    long idx = (long)blockIdx.x * 256 + threadIdx.x;
    if (blockIdx.x < PREP_XBLK) {
        int b = (int)(idx / KP), kp = (int)(idx % KP);
        float x = 0.f; int region = 3;
        if (kp < 146)      { x = g_X[b * NC + kp];        region = 0; }
        else if (kp < 292) { x = g_X[b * NC + kp - 146];  region = 0; }
        else if (kp < 438) { x = g_X[b * NC + kp - 292];  region = 2; }
        __nv_bfloat16 h = __float2bfloat16(x);
        __nv_bfloat16 o;
        if (region == 0) o = h;
        else if (region == 2) o = __float2bfloat16(x - __bfloat162float(h));
        else o = __float2bfloat16(0.f);
        g_Xb[b * KP + kp] = o;
    } else {
        long i2 = idx - (long)PREP_XBLK * 256;
        if (i2 >= (long)NCOL * KP) return;
        int n = (int)(i2 / KP), kp = (int)(i2 % KP);
        float c = 0.f; int region = 3;
        if (kp < 146)      { c = g_C[kp * NCOL + n];          region = 0; }
        else if (kp < 292) { c = g_C[(kp - 146) * NCOL + n];  region = 2; }
        else if (kp < 438) { c = g_C[(kp - 292) * NCOL + n];  region = 0; }
        __nv_bfloat16 h = __float2bfloat16(c);
        __nv_bfloat16 o;
        if (region == 0) o = h;
        else if (region == 2) o = __float2bfloat16(c - __bfloat162float(h));
        else o = __float2bfloat16(0.f);
        g_Ct[n * KP + kp] = o;
    }
}

// ============================================================
// kGemmW: warp-level mma.sync bf16 GEMM (HMMA; no 'a'-suffix needed).
// M[4096 x 784] = Xb[4096 x 448] @ Ct^T[448 x 784], fp32 accumulate.
// CTA tile 128x112, 8 warps (4M x 2N), warp tile 32x56 (2x7 mma),
// full K'=448 staged in smem with KPAD=456 (conflict-free frag LDS).
// ============================================================
#define MT 128
#define NT 112
#define SM_AB (MT * KPAD)                       // halves
#define SM_TOTAL ((MT + NT) * KPAD * 2)         // 218,880 bytes

__device__ __forceinline__ void mma16816(float* c, const uint32_t* a, const uint32_t* b) {
    asm volatile(
        "mma.sync.aligned.m16n8k16.row.col.f32.bf16.bf16.f32 "
        "{%0,%1,%2,%3}, {%4,%5,%6,%7}, {%8,%9}, {%0,%1,%2,%3};"
        : "+f"(c[0]), "+f"(c[1]), "+f"(c[2]), "+f"(c[3])
        : "r"(a[0]), "r"(a[1]), "r"(a[2]), "r"(a[3]), "r"(b[0]), "r"(b[1]));
}

__global__ void __launch_bounds__(256, 1) kGemmW(int B) {
    extern __shared__ __nv_bfloat16 sm[];        // As [128][456], Bs [112][456]
    __nv_bfloat16* As = sm;
    __nv_bfloat16* Bs = sm + SM_AB;
    int tid = threadIdx.x, wid = tid >> 5, lane = tid & 31;
    int b0 = blockIdx.x * MT, n0 = blockIdx.y * NT;

    // stage A: 128 rows x 448 halves (56 x 16B chunks per row)
    {
        const uint4* src = (const uint4*)(g_Xb + (size_t)b0 * KP);
        for (int i = tid; i < MT * 56; i += 256) {
            int row = i / 56, c = i - row * 56;
            *(uint4*)(As + row * KPAD + c * 8) = src[row * 56 + c];
        }
    }
    // stage B: 112 rows x 448 halves
    {
        const uint4* src = (const uint4*)(g_Ct + (size_t)n0 * KP);
        for (int i = tid; i < NT * 56; i += 256) {
            int row = i / 56, c = i - row * 56;
            *(uint4*)(Bs + row * KPAD + c * 8) = src[row * 56 + c];
        }
    }
    __syncthreads();

    int wm = (wid & 3) * 32;          // warp M offset
    int wn = (wid >> 2) * 56;         // warp N offset
    int qr = lane >> 2, qc = lane & 3;

    float acc[2][7][4];
    #pragma unroll
    for (int tm = 0; tm < 2; ++tm)
        #pragma unroll
        for (int tn = 0; tn < 7; ++tn)
            #pragma unroll
            for (int e = 0; e < 4; ++e) acc[tm][tn][e] = 0.f;

    #pragma unroll 2
    for (int k0 = 0; k0 < KP; k0 += 16) {
        uint32_t bf[7][2];
        #pragma unroll
        for (int tn = 0; tn < 7; ++tn) {
            const __nv_bfloat16* bp = Bs + (wn + tn * 8 + qr) * KPAD + k0 + qc * 2;
            bf[tn][0] = *(const uint32_t*)bp;
            bf[tn][1] = *(const uint32_t*)(bp + 8);
        }
        uint32_t af[2][4];
        #pragma unroll
        for (int tm = 0; tm < 2; ++tm) {
            const __nv_bfloat16* ap = As + (wm + tm * 16 + qr) * KPAD + k0 + qc * 2;
            af[tm][0] = *(const uint32_t*)ap;
            af[tm][1] = *(const uint32_t*)(ap + 8 * KPAD);
            af[tm][2] = *(const uint32_t*)(ap + 8);
            af[tm][3] = *(const uint32_t*)(ap + 8 * KPAD + 8);
        }
        #pragma unroll
        for (int tm = 0; tm < 2; ++tm)
            #pragma unroll
            for (int tn = 0; tn < 7; ++tn)
                mma16816(acc[tm][tn], af[tm], bf[tn]);
    }

    // epilogue: direct stores (col = even -> 8B-aligned float2)
    #pragma unroll
    for (int tm = 0; tm < 2; ++tm) {
        int row = b0 + wm + tm * 16 + qr;
        #pragma unroll
        for (int tn = 0; tn < 7; ++tn) {
            int col = n0 + wn + tn * 8 + qc * 2;
            if (row < B)
                *(float2*)&g_M[(size_t)row * NCOL + col] = make_float2(acc[tm][tn][0], acc[tm][tn][1]);
            if (row + 8 < B)
                *(float2*)&g_M[(size_t)(row + 8) * NCOL + col] = make_float2(acc[tm][tn][2], acc[tm][tn][3]);
        }
    }
}

// ============================================================
// kOut: assemble 21x3 joints per batch item; float4 staged loads.
// ============================================================
__global__ void kOut(const float* __restrict__ Wt, float* __restrict__ out, int B) {
    __shared__ float Ssm[256];
    __shared__ float Ms[8][784];
    __shared__ float As[8][192];
    int tid = threadIdx.x, warp = tid >> 5, lane = tid & 31;
    Ssm[tid] = g_S[tid];
    __syncthreads();
    int b = blockIdx.x * 8 + warp;
    if (b >= B) return;
    {
        const float4* mp = (const float4*)(g_M + (size_t)b * 784);
        float4* md = (float4*)Ms[warp];
        for (int i = lane; i < 196; i += 32) md[i] = mp[i];
        const float4* ap = (const float4*)(g_A + (size_t)b * 192);
        float4* ad = (float4*)As[warp];
        for (int i = lane; i < 48; i += 32) ad[i] = ap[i];
    }
    __syncwarp();
    if (lane < 21) {
        float a0 = 0.f, a1 = 0.f, a2 = 0.f;
        if (lane < 16) {
            int k = lane;
            #pragma unroll
            for (int j = 0; j < 16; ++j) {
                const float* Aj = &As[warp][j * 12];
                float s = Ssm[k * 16 + j];
                int base = (k * 16 + j) * 3;
                float m0 = Ms[warp][base], m1 = Ms[warp][base + 1], m2 = Ms[warp][base + 2];
                a0 += Aj[0] * m0 + Aj[1] * m1 + Aj[2] * m2 + Aj[9]  * s;
                a1 += Aj[3] * m0 + Aj[4] * m1 + Aj[5] * m2 + Aj[10] * s;
                a2 += Aj[6] * m0 + Aj[7] * m1 + Aj[8] * m2 + Aj[11] * s;
            }
        } else {
            int f = lane - 16;
            float v0 = Ms[warp][768 + f * 3], v1 = Ms[warp][768 + f * 3 + 1], v2 = Ms[warp][768 + f * 3 + 2];
            const float* wr = Wt + c_fidx[f] * 16;
            #pragma unroll
            for (int j = 0; j < 16; ++j) {
                const float* Aj = &As[warp][j * 12];
                float w = wr[j];
                a0 += w * (Aj[0] * v0 + Aj[1] * v1 + Aj[2] * v2 + Aj[9]);
                a1 += w * (Aj[3] * v0 + Aj[4] * v1 + Aj[5] * v2 + Aj[10]);
                a2 += w * (Aj[6] * v0 + Aj[7] * v1 + Aj[8] * v2 + Aj[11]);
            }
        }
        float* op = out + b * 63 + lane * 3;
        op[0] = a0; op[1] = a1; op[2] = a2;
    }
}

// ============================================================
extern "C" void kernel_launch(void* const* d_in, const int* in_sizes, int n_in,
                              void* d_out, int out_size) {
    const float* beta  = (const float*)d_in[0];
    const float* theta = (const float*)d_in[1];
    const float* vt    = (const float*)d_in[2];
    const float* sd    = (const float*)d_in[3];
    const float* pd    = (const float*)d_in[4];
    const float* Jreg  = (const float*)d_in[5];
    const float* W     = (const float*)d_in[6];
    const float* hm    = (const float*)d_in[7];
    const float* hc    = (const float*)d_in[8];
    int B = in_sizes[0] / 10;
    if (B > BMAX) B = BMAX;

    cudaFuncSetAttribute(kGemmW, cudaFuncAttributeMaxDynamicSharedMemorySize, SM_TOTAL);

    kC<<<NC, 256>>>(vt, sd, pd, Jreg, W);
    kBatch<<<(B + 7) / 8, 256>>>(beta, theta, hm, hc, B);
    int prepBlocks = PREP_XBLK + (NCOL * KP + 255) / 256;
    kPrep<<<prepBlocks, 256>>>(B);
    kGemmW<<<dim3((B + MT - 1) / MT, NCOL / NT), 256, SM_TOTAL>>>(B);
    kOut<<<(B + 7) / 8, 256>>>(W, (float*)d_out, B);
}

// round 7
// speedup vs baseline: 2.5088x; 1.4673x over previous
#include <cuda_runtime.h>
#include <cuda_bf16.h>
#include <cstdint>
#include <math.h>

#define NVV 778
#define NC   146      // 1 + 10 beta + 135 pose_feature
#define NCOL 784      // 768 joint cols + 15 finger cols + 1 pad
#define BMAX 4096
#define KP   448      // split-K: [Xh(146)|Xh(146)|Xl(146)|pad10]

// ---- scratch (static device globals; no allocation) ----
__device__ float g_S[256];
__device__ float g_JT[11 * 48];
__device__ float g_A[BMAX * 192];   // skinning transforms 16 x (R9 + t3)
__device__ float g_M[BMAX * NCOL];  // GEMM result
__device__ __nv_bfloat16 g_Xb[BMAX * KP];   // split-bf16 X, row-major [b][kp]
__device__ __nv_bfloat16 g_Ct[NCOL * KP];   // split-bf16 C^T, row-major [n][kp]

__constant__ int c_par[16]   = {-1,0,1,2,0,4,5,0,7,8,0,10,11,0,13,14};
__constant__ int c_depth[16] = {0,1,2,3,1,2,3,1,2,3,1,2,3,1,2,3};
__constant__ int c_fidx[5]   = {734,333,443,555,678};

__device__ __forceinline__ uint32_t smem_u32(const void* p) {
    uint32_t a;
    asm("{ .reg .u64 t; cvta.to.shared.u64 t, %1; cvt.u32.u64 %0, t; }" : "=r"(a) : "l"(p));
    return a;
}

// split val into bf16 hi/lo
__device__ __forceinline__ void bf16_split(float v, __nv_bfloat16& hi, __nv_bfloat16& lo) {
    hi = __float2bfloat16(v);
    lo = __float2bfloat16(v - __bfloat162float(hi));
}

// ============================================================
// kC: C[r, n] = sum_v Jreg[v,k]*w[v,j]*D[r, v*3+c], n=(k*16+j)*3+c
// Emits split-bf16 C^T directly:  Ct[n][kp] = [Ch | Cl | Ch | 0]
// + finger rows 768..782, + S (r==0), + JT (r<11).
// grid: NC blocks x 256 threads (thread = (k,j))
// ============================================================
#define CHV 112
__global__ void __launch_bounds__(256) kC(
        const float* __restrict__ vt, const float* __restrict__ sd,
        const float* __restrict__ pd, const float* __restrict__ Jreg,
        const float* __restrict__ Wt) {
    __shared__ float Ds[CHV * 3];
    __shared__ float Jr[CHV * 16];
    __shared__ float Wc[CHV * 16];
    int r = blockIdx.x, t = threadIdx.x;
    const float* src = (r == 0) ? vt : (r < 11 ? sd + (r - 1) * (NVV * 3)
                                               : pd + (r - 11) * (NVV * 3));
    int k = t >> 4, j = t & 15;
    int jj = t / 3, cc = t - jj * 3;
    int fgi = (t < 15) ? (c_fidx[t / 3] * 3 + (t % 3)) : -1;
    float a0 = 0.f, a1 = 0.f, a2 = 0.f, ss = 0.f, jt = 0.f, fingv = 0.f;

    for (int v0 = 0; v0 < NVV; v0 += CHV) {
        int n = NVV - v0; if (n > CHV) n = CHV;
        __syncthreads();
        for (int i = t; i < n * 3; i += 256) Ds[i] = src[v0 * 3 + i];
        for (int i = t; i < n * 16; i += 256) {
            Jr[i] = Jreg[v0 * 16 + i];
            Wc[i] = Wt[v0 * 16 + i];
        }
        __syncthreads();
        #pragma unroll 4
        for (int v = 0; v < n; ++v) {
            float e = Jr[v * 16 + k] * Wc[v * 16 + j];
            ss += e;
            a0 += e * Ds[v * 3 + 0];
            a1 += e * Ds[v * 3 + 1];
            a2 += e * Ds[v * 3 + 2];
        }
        if (r < 11 && t < 48) {
            #pragma unroll 4
            for (int v = 0; v < n; ++v) jt += Jr[v * 16 + jj] * Ds[v * 3 + cc];
        }
        if (fgi >= 0 && fgi >= v0 * 3 && fgi < (v0 + n) * 3) fingv = Ds[fgi - v0 * 3];
    }
    // split-store into Ct rows
    float vals[3] = {a0, a1, a2};
    #pragma unroll
    for (int c2 = 0; c2 < 3; ++c2) {
        int n = t * 3 + c2;
        __nv_bfloat16 hi, lo;
        bf16_split(vals[c2], hi, lo);
        g_Ct[(size_t)n * KP + r] = hi;
        g_Ct[(size_t)n * KP + 146 + r] = lo;
        g_Ct[(size_t)n * KP + 292 + r] = hi;
    }
    if (t < 15) {
        int n = 768 + t;
        __nv_bfloat16 hi, lo;
        bf16_split(fingv, hi, lo);
        g_Ct[(size_t)n * KP + r] = hi;
        g_Ct[(size_t)n * KP + 146 + r] = lo;
        g_Ct[(size_t)n * KP + 292 + r] = hi;
    }
    if (r == 0) {
        g_S[t] = ss;
        __nv_bfloat16 z = __float2bfloat16(0.f);
        for (int n = t; n < NCOL; n += 256)
            #pragma unroll
            for (int kp = 438; kp < KP; ++kp) g_Ct[(size_t)n * KP + kp] = z;
        for (int kp = t; kp < KP; kp += 256) g_Ct[(size_t)783 * KP + kp] = z;
    }
    if (r < 11 && t < 48) g_JT[r * 48 + t] = jt;
}

// ============================================================
// kBatch: per-batch kinematics; emits split-bf16 Xb row directly.
// ============================================================
__global__ void kBatch(const float* __restrict__ beta, const float* __restrict__ theta,
                       const float* __restrict__ hm, const float* __restrict__ hc, int B) {
    __shared__ float hcs[45 * 45];
    __shared__ float hms[45];
    __shared__ float JTs[11 * 48];
    __shared__ float wsPose[8][48];
    __shared__ float wsA[8][16 * 12];
    __shared__ float wsJ[8][48];
    __shared__ float wsBeta[8][10];
    __shared__ float wsX[8][146];

    int tid = threadIdx.x, warp = tid >> 5, lane = tid & 31;
    for (int i = tid; i < 2025; i += 256) hcs[i] = hc[i];
    if (tid < 45) hms[tid] = hm[tid];
    for (int i = tid; i < 528; i += 256) JTs[i] = g_JT[i];
    __syncthreads();

    int b = blockIdx.x * 8 + warp;
    if (b >= B) return;

    float* P = wsPose[warp];
    const float* th = theta + b * 48;
    if (lane < 16) { P[lane] = th[lane]; P[lane + 16] = th[lane + 16]; P[lane + 32] = th[lane + 32]; }
    if (lane < 10) wsBeta[warp][lane] = beta[b * 10 + lane];
    __syncwarp();

    int i0 = lane, i1 = lane + 32;
    float acc0 = hms[i0];
    float acc1 = (i1 < 45) ? hms[i1] : 0.f;
    #pragma unroll 5
    for (int p = 0; p < 45; ++p) {
        float tv = P[3 + p];
        acc0 += tv * hcs[p * 45 + i0];
        if (i1 < 45) acc1 += tv * hcs[p * 45 + i1];
    }
    __syncwarp();
    P[3 + i0] = acc0;
    if (i1 < 45) P[3 + i1] = acc1;
    __syncwarp();

    float* xs = wsX[warp];
    float R[9];
    if (lane < 16) {
        float rx = P[3 * lane], ry = P[3 * lane + 1], rz = P[3 * lane + 2];
        float ex = rx + 1e-8f, ey = ry + 1e-8f, ez = rz + 1e-8f;
        float ang = sqrtf(ex * ex + ey * ey + ez * ez);
        float inv = 1.0f / ang;
        float ax = rx * inv, ay = ry * inv, az = rz * inv;
        float s, co;
        sincosf(ang, &s, &co);
        float t1 = 1.0f - co;
        R[0] = 1.0f - t1 * (ay * ay + az * az);
        R[1] = -s * az + t1 * ax * ay;
        R[2] =  s * ay + t1 * ax * az;
        R[3] =  s * az + t1 * ax * ay;
        R[4] = 1.0f - t1 * (ax * ax + az * az);
        R[5] = -s * ax + t1 * ay * az;
        R[6] = -s * ay + t1 * ax * az;
        R[7] =  s * ax + t1 * ay * az;
        R[8] = 1.0f - t1 * (ax * ax + ay * ay);
        if (lane >= 1) {
            #pragma unroll
            for (int e = 0; e < 9; ++e)
                xs[11 + (lane - 1) * 9 + e] = R[e] - ((e == 0 || e == 4 || e == 8) ? 1.0f : 0.0f);
        }
    }
    if (lane == 0) xs[0] = 1.0f;
    if (lane < 10) xs[1 + lane] = wsBeta[warp][lane];
    __syncwarp();

    // split-bf16 Xb row: [Xh(146) | Xh(146) | Xl(146) | 0]
    {
        __nv_bfloat16* xb = g_Xb + (size_t)b * KP;
        for (int kp = lane; kp < KP; kp += 32) {
            __nv_bfloat16 o;
            if (kp < 146) o = __float2bfloat16(xs[kp]);
            else if (kp < 292) o = __float2bfloat16(xs[kp - 146]);
            else if (kp < 438) {
                float v = xs[kp - 292];
                __nv_bfloat16 h = __float2bfloat16(v);
                o = __float2bfloat16(v - __bfloat162float(h));
            } else o = __float2bfloat16(0.f);
            xb[kp] = o;
        }
    }

    float* Jv = wsJ[warp];
    for (int o = lane; o < 48; o += 32) {
        float acc = JTs[o];
        #pragma unroll
        for (int s2 = 0; s2 < 10; ++s2) acc += wsBeta[warp][s2] * JTs[(s2 + 1) * 48 + o];
        Jv[o] = acc;
    }
    __syncwarp();

    float AR[9], At[3];
    float tl0 = 0.f, tl1 = 0.f, tl2 = 0.f;
    if (lane < 16) {
        int par = c_par[lane];
        if (lane == 0) { tl0 = Jv[0]; tl1 = Jv[1]; tl2 = Jv[2]; }
        else {
            tl0 = Jv[3 * lane + 0] - Jv[3 * par + 0];
            tl1 = Jv[3 * lane + 1] - Jv[3 * par + 1];
            tl2 = Jv[3 * lane + 2] - Jv[3 * par + 2];
        }
    }
    float* Aw = wsA[warp];
    if (lane == 0) {
        #pragma unroll
        for (int e = 0; e < 9; ++e) { AR[e] = R[e]; Aw[e] = R[e]; }
        At[0] = tl0; At[1] = tl1; At[2] = tl2;
        Aw[9] = tl0; Aw[10] = tl1; Aw[11] = tl2;
    }
    __syncwarp();
    for (int level = 1; level <= 3; ++level) {
        if (lane < 16 && c_depth[lane] == level) {
            int par = c_par[lane];
            float Pp[12];
            #pragma unroll
            for (int e = 0; e < 12; ++e) Pp[e] = Aw[par * 12 + e];
            #pragma unroll
            for (int rr = 0; rr < 3; ++rr)
                #pragma unroll
                for (int ccx = 0; ccx < 3; ++ccx)
                    AR[rr * 3 + ccx] = Pp[rr * 3 + 0] * R[0 + ccx] +
                                       Pp[rr * 3 + 1] * R[3 + ccx] +
                                       Pp[rr * 3 + 2] * R[6 + ccx];
            At[0] = Pp[0] * tl0 + Pp[1] * tl1 + Pp[2] * tl2 + Pp[9];
            At[1] = Pp[3] * tl0 + Pp[4] * tl1 + Pp[5] * tl2 + Pp[10];
            At[2] = Pp[6] * tl0 + Pp[7] * tl1 + Pp[8] * tl2 + Pp[11];
            #pragma unroll
            for (int e = 0; e < 9; ++e) Aw[lane * 12 + e] = AR[e];
            Aw[lane * 12 + 9] = At[0]; Aw[lane * 12 + 10] = At[1]; Aw[lane * 12 + 11] = At[2];
        }
        __syncwarp();
    }
    if (lane < 16) {
        float jx = Jv[3 * lane], jy = Jv[3 * lane + 1], jz = Jv[3 * lane + 2];
        At[0] -= AR[0] * jx + AR[1] * jy + AR[2] * jz;
        At[1] -= AR[3] * jx + AR[4] * jy + AR[5] * jz;
        At[2] -= AR[6] * jx + AR[7] * jy + AR[8] * jz;
        float* ap = g_A + b * 192 + lane * 12;
        #pragma unroll
        for (int e = 0; e < 9; ++e) ap[e] = AR[e];
        ap[9] = At[0]; ap[10] = At[1]; ap[11] = At[2];
    }
}

// ============================================================
// kGemmW v2: mma.sync bf16 GEMM with 3-stage cp.async pipeline.
// CTA 128x112, K chunks of 64 (7 chunks), 34.6KB/stage x3 =
// 103.7KB smem -> 2 CTAs/SM resident.  Warp tile 32x56.
// ============================================================
#define MT 128
#define NT 112
#define KC 64
#define KCPAD 72
#define A_H (MT * KCPAD)          // 9216 halves
#define B_H (NT * KCPAD)          // 8064 halves
#define STG_H (A_H + B_H)         // 17280 halves / stage
#define NSTAGE 3
#define NCHUNK 7
#define SM_TOTAL (NSTAGE * STG_H * 2)   // 103,680 bytes

__device__ __forceinline__ void mma16816(float* c, const uint32_t* a, const uint32_t* b) {
    asm volatile(
        "mma.sync.aligned.m16n8k16.row.col.f32.bf16.bf16.f32 "
        "{%0,%1,%2,%3}, {%4,%5,%6,%7}, {%8,%9}, {%0,%1,%2,%3};"
        : "+f"(c[0]), "+f"(c[1]), "+f"(c[2]), "+f"(c[3])
        : "r"(a[0]), "r"(a[1]), "r"(a[2]), "r"(a[3]), "r"(b[0]), "r"(b[1]));
}

__global__ void __launch_bounds__(256, 2) kGemmW(int B) {
    extern __shared__ __nv_bfloat16 sm[];
    int tid = threadIdx.x, wid = tid >> 5, lane = tid & 31;
    int b0 = blockIdx.x * MT, n0 = blockIdx.y * NT;
    uint32_t sbase = smem_u32(sm);

    auto issue = [&](int c) {
        int s = c % NSTAGE;
        uint32_t abase = sbase + (uint32_t)(s * STG_H) * 2;
        uint32_t bbase = abase + A_H * 2;
        const char* ga = (const char*)g_Xb + (size_t)b0 * (KP * 2) + c * (KC * 2);
        #pragma unroll 1
        for (int i = tid; i < MT * 8; i += 256) {
            int row = i >> 3, cc = i & 7;
            uint32_t dst = abase + (uint32_t)(row * KCPAD + cc * 8) * 2;
            const char* src = ga + (size_t)row * (KP * 2) + cc * 16;
            asm volatile("cp.async.ca.shared.global [%0], [%1], 16;" :: "r"(dst), "l"(src));
        }
        const char* gb = (const char*)g_Ct + (size_t)n0 * (KP * 2) + c * (KC * 2);
        #pragma unroll 1
        for (int i = tid; i < NT * 8; i += 256) {
            int row = i >> 3, cc = i & 7;
            uint32_t dst = bbase + (uint32_t)(row * KCPAD + cc * 8) * 2;
            const char* src = gb + (size_t)row * (KP * 2) + cc * 16;
            asm volatile("cp.async.ca.shared.global [%0], [%1], 16;" :: "r"(dst), "l"(src));
        }
        asm volatile("cp.async.commit_group;");
    };

    int wm = (wid & 3) * 32;
    int wn = (wid >> 2) * 56;
    int qr = lane >> 2, qc = lane & 3;

    float acc[2][7][4];
    #pragma unroll
    for (int tm = 0; tm < 2; ++tm)
        #pragma unroll
        for (int tn = 0; tn < 7; ++tn)
            #pragma unroll
            for (int e = 0; e < 4; ++e) acc[tm][tn][e] = 0.f;

    issue(0); issue(1);

    for (int c = 0; c < NCHUNK; ++c) {
        if (c + 2 < NCHUNK) { issue(c + 2); asm volatile("cp.async.wait_group 2;"); }
        else if (c + 2 == NCHUNK) { asm volatile("cp.async.wait_group 1;"); }
        else { asm volatile("cp.async.wait_group 0;"); }
        __syncthreads();

        const __nv_bfloat16* As = sm + (c % NSTAGE) * STG_H;
        const __nv_bfloat16* Bs = As + A_H;
        #pragma unroll
        for (int k0 = 0; k0 < KC; k0 += 16) {
            uint32_t bf[7][2];
            #pragma unroll
            for (int tn = 0; tn < 7; ++tn) {
                const __nv_bfloat16* bp = Bs + (wn + tn * 8 + qr) * KCPAD + k0 + qc * 2;
                bf[tn][0] = *(const uint32_t*)bp;
                bf[tn][1] = *(const uint32_t*)(bp + 8);
            }
            uint32_t af[2][4];
            #pragma unroll
            for (int tm = 0; tm < 2; ++tm) {
                const __nv_bfloat16* ap = As + (wm + tm * 16 + qr) * KCPAD + k0 + qc * 2;
                af[tm][0] = *(const uint32_t*)ap;
                af[tm][1] = *(const uint32_t*)(ap + 8 * KCPAD);
                af[tm][2] = *(const uint32_t*)(ap + 8);
                af[tm][3] = *(const uint32_t*)(ap + 8 * KCPAD + 8);
            }
            #pragma unroll
            for (int tm = 0; tm < 2; ++tm)
                #pragma unroll
                for (int tn = 0; tn < 7; ++tn)
                    mma16816(acc[tm][tn], af[tm], bf[tn]);
        }
        __syncthreads();
    }

    #pragma unroll
    for (int tm = 0; tm < 2; ++tm) {
        int row = b0 + wm + tm * 16 + qr;
        #pragma unroll
        for (int tn = 0; tn < 7; ++tn) {
            int col = n0 + wn + tn * 8 + qc * 2;
            if (row < B)
                *(float2*)&g_M[(size_t)row * NCOL + col] = make_float2(acc[tm][tn][0], acc[tm][tn][1]);
            if (row + 8 < B)
                *(float2*)&g_M[(size_t)(row + 8) * NCOL + col] = make_float2(acc[tm][tn][2], acc[tm][tn][3]);
        }
    }
}

// ============================================================
// kOut: assemble 21x3 joints per batch item; float4 staged loads.
// ============================================================
__global__ void kOut(const float* __restrict__ Wt, float* __restrict__ out, int B) {
    __shared__ float Ssm[256];
    __shared__ float Ms[8][784];
    __shared__ float As[8][192];
    int tid = threadIdx.x, warp = tid >> 5, lane = tid & 31;
    Ssm[tid] = g_S[tid];
    __syncthreads();
    int b = blockIdx.x * 8 + warp;
    if (b >= B) return;
    {
        const float4* mp = (const float4*)(g_M + (size_t)b * 784);
        float4* md = (float4*)Ms[warp];
        for (int i = lane; i < 196; i += 32) md[i] = mp[i];
        const float4* ap = (const float4*)(g_A + (size_t)b * 192);
        float4* ad = (float4*)As[warp];
        for (int i = lane; i < 48; i += 32) ad[i] = ap[i];
    }
    __syncwarp();
    if (lane < 21) {
        float a0 = 0.f, a1 = 0.f, a2 = 0.f;
        if (lane < 16) {
            int k = lane;
            #pragma unroll
            for (int j = 0; j < 16; ++j) {
                const float* Aj = &As[warp][j * 12];
                float s = Ssm[k * 16 + j];
                int base = (k * 16 + j) * 3;
                float m0 = Ms[warp][base], m1 = Ms[warp][base + 1], m2 = Ms[warp][base + 2];
                a0 += Aj[0] * m0 + Aj[1] * m1 + Aj[2] * m2 + Aj[9]  * s;
                a1 += Aj[3] * m0 + Aj[4] * m1 + Aj[5] * m2 + Aj[10] * s;
                a2 += Aj[6] * m0 + Aj[7] * m1 + Aj[8] * m2 + Aj[11] * s;
            }
        } else {
            int f = lane - 16;
            float v0 = Ms[warp][768 + f * 3], v1 = Ms[warp][768 + f * 3 + 1], v2 = Ms[warp][768 + f * 3 + 2];
            const float* wr = Wt + c_fidx[f] * 16;
            #pragma unroll
            for (int j = 0; j < 16; ++j) {
                const float* Aj = &As[warp][j * 12];
                float w = wr[j];
                a0 += w * (Aj[0] * v0 + Aj[1] * v1 + Aj[2] * v2 + Aj[9]);
                a1 += w * (Aj[3] * v0 + Aj[4] * v1 + Aj[5] * v2 + Aj[10]);
                a2 += w * (Aj[6] * v0 + Aj[7] * v1 + Aj[8] * v2 + Aj[11]);
            }
        }
        float* op = out + b * 63 + lane * 3;
        op[0] = a0; op[1] = a1; op[2] = a2;
    }
}

// ============================================================
extern "C" void kernel_launch(void* const* d_in, const int* in_sizes, int n_in,
                              void* d_out, int out_size) {
    const float* beta  = (const float*)d_in[0];
    const float* theta = (const float*)d_in[1];
    const float* vt    = (const float*)d_in[2];
    const float* sd    = (const float*)d_in[3];
    const float* pd    = (const float*)d_in[4];
    const float* Jreg  = (const float*)d_in[5];
    const float* W     = (const float*)d_in[6];
    const float* hm    = (const float*)d_in[7];
    const float* hc    = (const float*)d_in[8];
    int B = in_sizes[0] / 10;
    if (B > BMAX) B = BMAX;

    cudaFuncSetAttribute(kGemmW, cudaFuncAttributeMaxDynamicSharedMemorySize, SM_TOTAL);

    kC<<<NC, 256>>>(vt, sd, pd, Jreg, W);
    kBatch<<<(B + 7) / 8, 256>>>(beta, theta, hm, hc, B);
    kGemmW<<<dim3((B + MT - 1) / MT, NCOL / NT), 256, SM_TOTAL>>>(B);
    kOut<<<(B + 7) / 8, 256>>>(W, (float*)d_out, B);
}